// round 11
// baseline (speedup 1.0000x reference)
#include <cuda_runtime.h>
#include <math.h>

#define NE 8
#define NC 1000
#define DFEAT 59
#define NH1 256
#define NH2 128
#define TPB 16            // tokens per block
#define LN2F 0.69314718055994530942f

__device__ __forceinline__ float clipf(float x) {
    return fminf(fmaxf(x, -100.0f), 100.0f);
}

__device__ __forceinline__ float warp_sum(float v) {
    #pragma unroll
    for (int o = 16; o; o >>= 1) v += __shfl_xor_sync(0xffffffffu, v, o);
    return v;
}

// packed f32x2 FMA (Blackwell): acc.lo += a.lo*b.lo; acc.hi += a.hi*b.hi
__device__ __forceinline__ void ffma2(unsigned long long& acc,
                                      unsigned long long a, unsigned long long b) {
    asm("fma.rn.f32x2 %0, %1, %2, %0;" : "+l"(acc) : "l"(a), "l"(b));
}
__device__ __forceinline__ unsigned long long pack2(float lo, float hi) {
    unsigned long long r;
    asm("mov.b64 %0, {%1, %2};" : "=l"(r) : "f"(lo), "f"(hi));
    return r;
}
__device__ __forceinline__ float2 unpack2(unsigned long long v) {
    float2 r;
    asm("mov.b64 {%0, %1}, %2;" : "=f"(r.x), "=f"(r.y) : "l"(v));
    return r;
}

union F4U2 { float4 f; ulonglong2 u; };

// ---------------------------------------------------------------------------
// Mega kernel: features + 3-layer MLP for 16 tokens per block. 256 threads.
// ---------------------------------------------------------------------------
__global__ __launch_bounds__(256) void mega_kernel(
    const float* __restrict__ post,
    const float* __restrict__ W1, const float* __restrict__ b1,
    const float* __restrict__ g1, const float* __restrict__ be1,
    const float* __restrict__ W2, const float* __restrict__ b2,
    const float* __restrict__ g2, const float* __restrict__ be2,
    const float* __restrict__ W3, const float* __restrict__ b3,
    float* __restrict__ weights, float* __restrict__ logits,
    float* __restrict__ featsOut)
{
    // union: feat-phase buffers alias the GEMM1 output buffer
    __shared__ __align__(16) float smem_u[TPB * 260];  // 16640 B
    float* s_mp  = smem_u;          // [1024] mean over experts (+pad)
    float* s_lmp = smem_u + 1024;   // [1024] log2(mean+eps)    (+pad)
    float* sh    = smem_u;          // [TPB*260] h1 (MLP phase)

    __shared__ __align__(16) float sfeat[TPB * 60];   // clipped features
    __shared__ __align__(16) float sh2[TPB * 132];    // h2
    __shared__ float sW3[8 * NH2];                    // W3 transposed [e][k]
    __shared__ float red[24];
    __shared__ float s_maxp[NE];
    __shared__ float s_glob[3];
    __shared__ float sb3[8];

    const int t0   = blockIdx.x * TPB;
    const int tid  = threadIdx.x;
    const int lane = tid & 31;
    const int w    = tid >> 5;

    // stage W3 transposed + b3 (read during GEMM3, after many syncs)
    for (int i = tid; i < NH2 * 8; i += 256) {
        int k = i >> 3, e = i & 7;
        sW3[e * NH2 + k] = W3[i];
    }
    if (tid < 8) sb3[tid] = b3[tid];

    // =====================================================================
    // Phase 1: features, one token at a time
    // =====================================================================
    for (int tl = 0; tl < TPB; tl++) {
        const int tg = t0 + tl;
        const float4* base = (const float4*)(post + (size_t)tg * (NE * NC));

        // ---- pass A: thread tid<250 owns classes 4*tid..4*tid+3 ----
        float a_var = 0.0f, a_ment = 0.0f, a_mn2 = 0.0f;
        if (tid < 250) {
            float4 v = base[tid];
            float sx = v.x, sy = v.y, sz = v.z, sw = v.w;
            float qx = v.x * v.x, qy = v.y * v.y, qz = v.z * v.z, qw = v.w * v.w;
            #pragma unroll
            for (int e = 1; e < 8; e++) {
                v = base[e * 250 + tid];
                sx += v.x; sy += v.y; sz += v.z; sw += v.w;
                qx = fmaf(v.x, v.x, qx); qy = fmaf(v.y, v.y, qy);
                qz = fmaf(v.z, v.z, qz); qw = fmaf(v.w, v.w, qw);
            }
            float m[4] = {sx * 0.125f, sy * 0.125f, sz * 0.125f, sw * 0.125f};
            float q[4] = {qx, qy, qz, qw};
            float lm[4];
            #pragma unroll
            for (int j = 0; j < 4; j++) {
                lm[j] = __log2f(m[j] + 1e-8f);
                a_var += fmaf(-8.0f * m[j], m[j], q[j]) * (1.0f / 7.0f);
                a_ment = fmaf(m[j], lm[j], a_ment);
                a_mn2  = fmaf(m[j], m[j], a_mn2);
            }
            float4 m4; m4.x = m[0];  m4.y = m[1];  m4.z = m[2];  m4.w = m[3];
            float4 l4; l4.x = lm[0]; l4.y = lm[1]; l4.z = lm[2]; l4.w = lm[3];
            ((float4*)s_mp)[tid]  = m4;
            ((float4*)s_lmp)[tid] = l4;
        } else {
            float4 z = make_float4(0.f, 0.f, 0.f, 0.f);
            ((float4*)s_mp)[tid]  = z;
            ((float4*)s_lmp)[tid] = z;
        }
        a_var  = warp_sum(a_var);
        a_ment = warp_sum(a_ment);
        a_mn2  = warp_sum(a_mn2);
        if (lane == 0) { red[w] = a_var; red[8 + w] = a_ment; red[16 + w] = a_mn2; }
        __syncthreads();
        if (tid == 0) {
            float v = 0.0f, me = 0.0f, mn2 = 0.0f;
            #pragma unroll
            for (int i = 0; i < 8; i++) { v += red[i]; me += red[8 + i]; mn2 += red[16 + i]; }
            s_glob[0] = v; s_glob[1] = me; s_glob[2] = mn2;
        }
        __syncthreads();

        // ---- pass B: warp w = expert w (GMEM re-read, L1-hot) ----
        {
            const int e = w;
            const float4* prow = base + e * 250;
            unsigned long long splp = 0ull, an2 = 0ull, adot = 0ull, aklb = 0ull;
            float t_0 = -1e30f, t_1 = -1e30f, t_2 = -1e30f, t_3 = -1e30f, t_4 = -1e30f;

            #pragma unroll
            for (int k = 0; k < 8; k++) {
                const int q = lane + 32 * k;
                F4U2 pv;
                if (q < 250) pv.f = __ldg(prow + q);
                else         pv.f = make_float4(0.f, 0.f, 0.f, 0.f);
                F4U2 mv, lv;
                mv.u = ((const ulonglong2*)s_mp)[q];
                lv.u = ((const ulonglong2*)s_lmp)[q];

                float lp0 = __log2f(pv.f.x + 1e-8f);
                float lp1 = __log2f(pv.f.y + 1e-8f);
                float lp2 = __log2f(pv.f.z + 1e-8f);
                float lp3 = __log2f(pv.f.w + 1e-8f);
                unsigned long long lp01 = pack2(lp0, lp1);
                unsigned long long lp23 = pack2(lp2, lp3);

                ffma2(splp, pv.u.x, lp01);   ffma2(splp, pv.u.y, lp23);
                ffma2(an2,  pv.u.x, pv.u.x); ffma2(an2,  pv.u.y, pv.u.y);
                ffma2(adot, pv.u.x, mv.u.x); ffma2(adot, pv.u.y, mv.u.y);
                ffma2(aklb, pv.u.x, lv.u.x); ffma2(aklb, pv.u.y, lv.u.y);

                #define TOP5_INS(P) { \
                    float c1 = fminf(t_0, (P)); t_0 = fmaxf(t_0, (P)); \
                    float c2 = fminf(t_1, c1);  t_1 = fmaxf(t_1, c1); \
                    float c3 = fminf(t_2, c2);  t_2 = fmaxf(t_2, c2); \
                    float c4 = fminf(t_3, c3);  t_3 = fmaxf(t_3, c3); \
                    t_4 = fmaxf(t_4, c4); }
                TOP5_INS(pv.f.x) TOP5_INS(pv.f.y) TOP5_INS(pv.f.z) TOP5_INS(pv.f.w)
                #undef TOP5_INS
            }

            float2 u;
            u = unpack2(splp); float s_plp = u.x + u.y;
            u = unpack2(an2);  float n2    = u.x + u.y;
            u = unpack2(adot); float dot   = u.x + u.y;
            u = unpack2(aklb); float klb   = u.x + u.y;
            s_plp = warp_sum(s_plp);
            n2    = warp_sum(n2);
            dot   = warp_sum(dot);
            klb   = warp_sum(klb);

            // merge lane-local top-5: 5 rounds of warp argmax, winner pops
            int kk = 0;
            float tkl[5];
            #pragma unroll
            for (int r = 0; r < 5; r++) {
                float cand = (kk == 0) ? t_0 : (kk == 1) ? t_1 : (kk == 2) ? t_2
                           : (kk == 3) ? t_3 : (kk == 4) ? t_4 : -1e30f;
                float best = cand;
                int bl = lane;
                #pragma unroll
                for (int o = 16; o; o >>= 1) {
                    float ov = __shfl_xor_sync(0xffffffffu, best, o);
                    int   ol = __shfl_xor_sync(0xffffffffu, bl, o);
                    if (ov > best || (ov == best && ol < bl)) { best = ov; bl = ol; }
                }
                tkl[r] = best;
                if (lane == bl) kk++;
            }

            if (lane == 0) {
                float tk0 = tkl[0], tk1 = tkl[1];
                float mass = tkl[0] + tkl[1] + tkl[2] + tkl[3] + tkl[4];
                float ent  = -LN2F * s_plp;
                float kl   = LN2F * (s_plp - klb);
                float pn   = fmaxf(sqrtf(n2), 1e-8f);
                float mn   = fmaxf(sqrtf(s_glob[2]), 1e-8f);
                float cosv = dot / (pn * mn);
                float f0 = clipf(ent);
                float f1 = clipf(mass);
                float f2 = clipf(1.0f - mass);
                float f3 = clipf(tk0);
                float f4 = clipf(tk0 - tk1);
                float f5 = clipf(cosv);
                float f6 = clipf(kl);
                float* fs = sfeat + tl * 60;
                fs[0 * 8 + e] = f0; fs[1 * 8 + e] = f1; fs[2 * 8 + e] = f2;
                fs[3 * 8 + e] = f3; fs[4 * 8 + e] = f4; fs[5 * 8 + e] = f5;
                fs[6 * 8 + e] = f6;
                float* fr = featsOut + (size_t)tg * DFEAT;
                fr[0 * 8 + e] = f0; fr[1 * 8 + e] = f1; fr[2 * 8 + e] = f2;
                fr[3 * 8 + e] = f3; fr[4 * 8 + e] = f4; fr[5 * 8 + e] = f5;
                fr[6 * 8 + e] = f6;
                s_maxp[e] = tk0;
            }
        }
        __syncthreads();

        if (tid == 0) {
            float s = 0.0f;
            #pragma unroll
            for (int e = 0; e < NE; e++) s += s_maxp[e];
            float mean = s * 0.125f;
            float ss = 0.0f;
            #pragma unroll
            for (int e = 0; e < NE; e++) { float d = s_maxp[e] - mean; ss = fmaf(d, d, ss); }
            float stdm = sqrtf(ss * (1.0f / 7.0f));
            float f56 = clipf(-LN2F * s_glob[1]);
            float f57 = clipf(s_glob[0] * (1.0f / NC));
            float f58 = clipf(stdm);
            float* fs = sfeat + tl * 60;
            fs[56] = f56; fs[57] = f57; fs[58] = f58;
            float* fr = featsOut + (size_t)tg * DFEAT;
            fr[56] = f56; fr[57] = f57; fr[58] = f58;
        }
        __syncthreads();   // protect s_mp/s_lmp/s_glob before next token
    }
    // sfeat complete; s_mp/s_lmp dead -> sh may be written
    __syncthreads();

    // =====================================================================
    // Phase 2: MLP. thread = (token tt = lane&15, col-group)
    // W loads are lane-broadcast (16 lanes share each address).
    // =====================================================================
    const int tt   = lane & 15;
    const int half = lane >> 4;

    // ---- GEMM1: 16 cols per thread, f32x2 accumulate ----
    {
        const int j0 = (w * 2 + half) * 16;
        unsigned long long acc[8];
        #pragma unroll
        for (int i = 0; i < 8; i++) acc[i] = 0ull;

        #pragma unroll 4
        for (int k = 0; k < DFEAT; k++) {
            const float* wr = W1 + k * NH1 + j0;
            F4U2 w0, w1, w2, w3;
            w0.f = *(const float4*)(wr);
            w1.f = *(const float4*)(wr + 4);
            w2.f = *(const float4*)(wr + 8);
            w3.f = *(const float4*)(wr + 12);
            float f = sfeat[tt * 60 + k];
            unsigned long long ff = pack2(f, f);
            ffma2(acc[0], w0.u.x, ff); ffma2(acc[1], w0.u.y, ff);
            ffma2(acc[2], w1.u.x, ff); ffma2(acc[3], w1.u.y, ff);
            ffma2(acc[4], w2.u.x, ff); ffma2(acc[5], w2.u.y, ff);
            ffma2(acc[6], w3.u.x, ff); ffma2(acc[7], w3.u.y, ff);
        }
        #pragma unroll
        for (int m = 0; m < 4; m++) {
            float4 bb = *(const float4*)(b1 + j0 + m * 4);
            float2 lo = unpack2(acc[2 * m]);
            float2 hi = unpack2(acc[2 * m + 1]);
            float4 o;
            o.x = lo.x + bb.x; o.y = lo.y + bb.y;
            o.z = hi.x + bb.z; o.w = hi.y + bb.w;
            *(float4*)(sh + tt * 260 + j0 + m * 4) = o;
        }
    }
    __syncthreads();

    // ---- LN1 + ReLU: warp w handles tokens 2w, 2w+1 ----
    #pragma unroll
    for (int a = 0; a < 2; a++) {
        int T = 2 * w + a;
        float* row = sh + T * 260;
        const int j0 = lane * 8;
        float4 v0 = *(float4*)(row + j0);
        float4 v1 = *(float4*)(row + j0 + 4);
        float s = v0.x + v0.y + v0.z + v0.w + v1.x + v1.y + v1.z + v1.w;
        s = warp_sum(s);
        float mu = s * (1.0f / NH1);
        float vs = 0.0f;
        vs = fmaf(v0.x - mu, v0.x - mu, vs); vs = fmaf(v0.y - mu, v0.y - mu, vs);
        vs = fmaf(v0.z - mu, v0.z - mu, vs); vs = fmaf(v0.w - mu, v0.w - mu, vs);
        vs = fmaf(v1.x - mu, v1.x - mu, vs); vs = fmaf(v1.y - mu, v1.y - mu, vs);
        vs = fmaf(v1.z - mu, v1.z - mu, vs); vs = fmaf(v1.w - mu, v1.w - mu, vs);
        vs = warp_sum(vs);
        float inv = rsqrtf(vs * (1.0f / NH1) + 1e-5f);
        float4 gg0 = *(const float4*)(g1 + j0);
        float4 gg1 = *(const float4*)(g1 + j0 + 4);
        float4 bb0 = *(const float4*)(be1 + j0);
        float4 bb1 = *(const float4*)(be1 + j0 + 4);
        float4 o0, o1;
        o0.x = fmaxf((v0.x - mu) * inv * gg0.x + bb0.x, 0.0f);
        o0.y = fmaxf((v0.y - mu) * inv * gg0.y + bb0.y, 0.0f);
        o0.z = fmaxf((v0.z - mu) * inv * gg0.z + bb0.z, 0.0f);
        o0.w = fmaxf((v0.w - mu) * inv * gg0.w + bb0.w, 0.0f);
        o1.x = fmaxf((v1.x - mu) * inv * gg1.x + bb1.x, 0.0f);
        o1.y = fmaxf((v1.y - mu) * inv * gg1.y + bb1.y, 0.0f);
        o1.z = fmaxf((v1.z - mu) * inv * gg1.z + bb1.z, 0.0f);
        o1.w = fmaxf((v1.w - mu) * inv * gg1.w + bb1.w, 0.0f);
        *(float4*)(row + j0)     = o0;
        *(float4*)(row + j0 + 4) = o1;
    }
    __syncthreads();

    // ---- GEMM2: 8 cols per thread, f32x2 ----
    {
        const int j0 = (w * 2 + half) * 8;
        unsigned long long acc[4];
        #pragma unroll
        for (int i = 0; i < 4; i++) acc[i] = 0ull;

        const float* frow = sh + tt * 260;
        #pragma unroll 4
        for (int k = 0; k < NH1; k++) {
            const float* wr = W2 + k * NH2 + j0;
            F4U2 w0, w1;
            w0.f = *(const float4*)(wr);
            w1.f = *(const float4*)(wr + 4);
            float f = frow[k];
            unsigned long long ff = pack2(f, f);
            ffma2(acc[0], w0.u.x, ff); ffma2(acc[1], w0.u.y, ff);
            ffma2(acc[2], w1.u.x, ff); ffma2(acc[3], w1.u.y, ff);
        }
        #pragma unroll
        for (int m = 0; m < 2; m++) {
            float4 bb = *(const float4*)(b2 + j0 + m * 4);
            float2 lo = unpack2(acc[2 * m]);
            float2 hi = unpack2(acc[2 * m + 1]);
            float4 o;
            o.x = lo.x + bb.x; o.y = lo.y + bb.y;
            o.z = hi.x + bb.z; o.w = hi.y + bb.w;
            *(float4*)(sh2 + tt * 132 + j0 + m * 4) = o;
        }
    }
    __syncthreads();

    // ---- LN2 + ReLU + GEMM3 + softmax: warp w handles tokens 2w, 2w+1 ----
    #pragma unroll
    for (int a = 0; a < 2; a++) {
        int T = 2 * w + a;
        float* row = sh2 + T * 132;
        const int j0 = lane * 4;
        float4 v = *(float4*)(row + j0);
        float s = v.x + v.y + v.z + v.w;
        s = warp_sum(s);
        float mu = s * (1.0f / NH2);
        float vs = 0.0f;
        vs = fmaf(v.x - mu, v.x - mu, vs); vs = fmaf(v.y - mu, v.y - mu, vs);
        vs = fmaf(v.z - mu, v.z - mu, vs); vs = fmaf(v.w - mu, v.w - mu, vs);
        vs = warp_sum(vs);
        float inv = rsqrtf(vs * (1.0f / NH2) + 1e-5f);
        float4 gg = *(const float4*)(g2 + j0);
        float4 bb = *(const float4*)(be2 + j0);
        float4 h;
        h.x = fmaxf((v.x - mu) * inv * gg.x + bb.x, 0.0f);
        h.y = fmaxf((v.y - mu) * inv * gg.y + bb.y, 0.0f);
        h.z = fmaxf((v.z - mu) * inv * gg.z + bb.z, 0.0f);
        h.w = fmaxf((v.w - mu) * inv * gg.w + bb.w, 0.0f);

        // GEMM3: each lane holds h for k = j0..j0+3
        float acc[8];
        #pragma unroll
        for (int e = 0; e < 8; e++) {
            const float* w3r = sW3 + e * NH2 + j0;
            float t = h.x * w3r[0];
            t = fmaf(h.y, w3r[1], t);
            t = fmaf(h.z, w3r[2], t);
            t = fmaf(h.w, w3r[3], t);
            acc[e] = warp_sum(t);
        }

        if (lane == 0) {
            int tg = t0 + T;
            float lg[8];
            float mx = -1e30f;
            #pragma unroll
            for (int e = 0; e < 8; e++) { lg[e] = acc[e] + sb3[e]; mx = fmaxf(mx, lg[e]); }
            float ex[8];
            float ssum = 0.0f;
            #pragma unroll
            for (int e = 0; e < 8; e++) { ex[e] = __expf(lg[e] - mx); ssum += ex[e]; }
            float invs = 1.0f / ssum;
            float4* lgo = (float4*)(logits + (size_t)tg * 8);
            float4* wgo = (float4*)(weights + (size_t)tg * 8);
            float4 o;
            o.x = lg[0]; o.y = lg[1]; o.z = lg[2]; o.w = lg[3]; lgo[0] = o;
            o.x = lg[4]; o.y = lg[5]; o.z = lg[6]; o.w = lg[7]; lgo[1] = o;
            o.x = ex[0] * invs; o.y = ex[1] * invs; o.z = ex[2] * invs; o.w = ex[3] * invs; wgo[0] = o;
            o.x = ex[4] * invs; o.y = ex[5] * invs; o.z = ex[6] * invs; o.w = ex[7] * invs; wgo[1] = o;
        }
    }
}

// ---------------------------------------------------------------------------
extern "C" void kernel_launch(void* const* d_in, const int* in_sizes, int n_in,
                              void* d_out, int out_size)
{
    const float* post = (const float*)d_in[0];
    const float* W1   = (const float*)d_in[1];
    const float* b1   = (const float*)d_in[2];
    const float* g1   = (const float*)d_in[3];
    const float* be1  = (const float*)d_in[4];
    const float* W2   = (const float*)d_in[5];
    const float* b2   = (const float*)d_in[6];
    const float* g2   = (const float*)d_in[7];
    const float* be2  = (const float*)d_in[8];
    const float* W3   = (const float*)d_in[9];
    const float* b3   = (const float*)d_in[10];

    const int B = in_sizes[0] / (NE * NC);

    float* out     = (float*)d_out;
    float* weights = out;                       // (B, 8)
    float* logits  = out + (size_t)B * 8;       // (B, 8)
    float* feats   = out + (size_t)B * 16;      // (B, 59)

    mega_kernel<<<B / TPB, 256>>>(post, W1, b1, g1, be1, W2, b2, g2, be2,
                                  W3, b3, weights, logits, feats);
}

// round 12
// speedup vs baseline: 1.0667x; 1.0667x over previous
#include <cuda_runtime.h>
#include <math.h>

#define NE 8
#define NC 1000
#define DFEAT 59
#define NH1 256
#define NH2 128
#define TPB 16            // tokens per block (MLP kernel)
#define LN2F 0.69314718055994530942f

__device__ __forceinline__ float clipf(float x) {
    return fminf(fmaxf(x, -100.0f), 100.0f);
}

__device__ __forceinline__ float warp_sum(float v) {
    #pragma unroll
    for (int o = 16; o; o >>= 1) v += __shfl_xor_sync(0xffffffffu, v, o);
    return v;
}

// packed f32x2 FMA (Blackwell): acc.lo += a.lo*b.lo; acc.hi += a.hi*b.hi
__device__ __forceinline__ void ffma2(unsigned long long& acc,
                                      unsigned long long a, unsigned long long b) {
    asm("fma.rn.f32x2 %0, %1, %2, %0;" : "+l"(acc) : "l"(a), "l"(b));
}
__device__ __forceinline__ unsigned long long pack2(float lo, float hi) {
    unsigned long long r;
    asm("mov.b64 %0, {%1, %2};" : "=l"(r) : "f"(lo), "f"(hi));
    return r;
}
__device__ __forceinline__ float2 unpack2(unsigned long long v) {
    float2 r;
    asm("mov.b64 {%0, %1}, %2;" : "=f"(r.x), "=f"(r.y) : "l"(v));
    return r;
}

union F4U2 { float4 f; ulonglong2 u; };

// ---------------------------------------------------------------------------
// Kernel 1: feature extraction (r10 version — known 154us / correct).
// One block per token, 256 threads (8 warps). No SMEM tile.
// ---------------------------------------------------------------------------
__global__ __launch_bounds__(256) void feat_kernel(
    const float* __restrict__ post, float* __restrict__ outFeats)
{
    __shared__ __align__(16) float s_mp[1024];   // mean over experts (+pad)
    __shared__ __align__(16) float s_lmp[1024];  // log2(mean+eps)    (+pad)
    __shared__ float red[24];
    __shared__ float s_maxp[NE];
    __shared__ float s_glob[3];  // [sum class var, sum m*l2m, sum m^2]

    const int t    = blockIdx.x;
    const int tid  = threadIdx.x;
    const int lane = tid & 31;
    const int w    = tid >> 5;

    const float4* base = (const float4*)(post + (size_t)t * (NE * NC)); // 2000 float4

    // ---- pass A: thread tid<250 owns classes 4*tid..4*tid+3, all 8 experts ----
    float a_var = 0.0f, a_ment = 0.0f, a_mn2 = 0.0f;
    if (tid < 250) {
        float4 v = base[tid];
        float sx = v.x, sy = v.y, sz = v.z, sw = v.w;
        float qx = v.x * v.x, qy = v.y * v.y, qz = v.z * v.z, qw = v.w * v.w;
        #pragma unroll
        for (int e = 1; e < 8; e++) {
            v = base[e * 250 + tid];
            sx += v.x; sy += v.y; sz += v.z; sw += v.w;
            qx = fmaf(v.x, v.x, qx); qy = fmaf(v.y, v.y, qy);
            qz = fmaf(v.z, v.z, qz); qw = fmaf(v.w, v.w, qw);
        }
        float m[4] = {sx * 0.125f, sy * 0.125f, sz * 0.125f, sw * 0.125f};
        float q[4] = {qx, qy, qz, qw};
        float lm[4];
        #pragma unroll
        for (int j = 0; j < 4; j++) {
            lm[j] = __log2f(m[j] + 1e-8f);
            a_var += fmaf(-8.0f * m[j], m[j], q[j]) * (1.0f / 7.0f);
            a_ment = fmaf(m[j], lm[j], a_ment);
            a_mn2  = fmaf(m[j], m[j], a_mn2);
        }
        float4 m4; m4.x = m[0];  m4.y = m[1];  m4.z = m[2];  m4.w = m[3];
        float4 l4; l4.x = lm[0]; l4.y = lm[1]; l4.z = lm[2]; l4.w = lm[3];
        ((float4*)s_mp)[tid]  = m4;
        ((float4*)s_lmp)[tid] = l4;
    } else {
        float4 z = make_float4(0.f, 0.f, 0.f, 0.f);
        ((float4*)s_mp)[tid]  = z;
        ((float4*)s_lmp)[tid] = z;
    }
    a_var  = warp_sum(a_var);
    a_ment = warp_sum(a_ment);
    a_mn2  = warp_sum(a_mn2);
    if (lane == 0) { red[w] = a_var; red[8 + w] = a_ment; red[16 + w] = a_mn2; }
    __syncthreads();
    if (tid == 0) {
        float v = 0.0f, me = 0.0f, mn2 = 0.0f;
        #pragma unroll
        for (int i = 0; i < 8; i++) { v += red[i]; me += red[8 + i]; mn2 += red[16 + i]; }
        s_glob[0] = v; s_glob[1] = me; s_glob[2] = mn2;
    }
    __syncthreads();

    // ---- pass B: warp w = expert w; GMEM re-read (L1/L2 hit) ----
    {
        const int e = w;
        const float4* prow = base + e * 250;
        unsigned long long splp = 0ull, an2 = 0ull, adot = 0ull, aklb = 0ull;
        float t_0 = -1e30f, t_1 = -1e30f, t_2 = -1e30f, t_3 = -1e30f, t_4 = -1e30f;

        #pragma unroll
        for (int k = 0; k < 8; k++) {
            const int q = lane + 32 * k;
            F4U2 pv;
            if (q < 250) pv.f = __ldg(prow + q);
            else         pv.f = make_float4(0.f, 0.f, 0.f, 0.f);
            F4U2 mv, lv;
            mv.u = ((const ulonglong2*)s_mp)[q];
            lv.u = ((const ulonglong2*)s_lmp)[q];

            float lp0 = __log2f(pv.f.x + 1e-8f);
            float lp1 = __log2f(pv.f.y + 1e-8f);
            float lp2 = __log2f(pv.f.z + 1e-8f);
            float lp3 = __log2f(pv.f.w + 1e-8f);
            unsigned long long lp01 = pack2(lp0, lp1);
            unsigned long long lp23 = pack2(lp2, lp3);

            ffma2(splp, pv.u.x, lp01);   ffma2(splp, pv.u.y, lp23);
            ffma2(an2,  pv.u.x, pv.u.x); ffma2(an2,  pv.u.y, pv.u.y);
            ffma2(adot, pv.u.x, mv.u.x); ffma2(adot, pv.u.y, mv.u.y);
            ffma2(aklb, pv.u.x, lv.u.x); ffma2(aklb, pv.u.y, lv.u.y);

            #define TOP5_INS(P) { \
                float c1 = fminf(t_0, (P)); t_0 = fmaxf(t_0, (P)); \
                float c2 = fminf(t_1, c1);  t_1 = fmaxf(t_1, c1); \
                float c3 = fminf(t_2, c2);  t_2 = fmaxf(t_2, c2); \
                float c4 = fminf(t_3, c3);  t_3 = fmaxf(t_3, c3); \
                t_4 = fmaxf(t_4, c4); }
            TOP5_INS(pv.f.x) TOP5_INS(pv.f.y) TOP5_INS(pv.f.z) TOP5_INS(pv.f.w)
            #undef TOP5_INS
        }

        float2 u;
        u = unpack2(splp); float s_plp = u.x + u.y;
        u = unpack2(an2);  float n2    = u.x + u.y;
        u = unpack2(adot); float dot   = u.x + u.y;
        u = unpack2(aklb); float klb   = u.x + u.y;
        s_plp = warp_sum(s_plp);
        n2    = warp_sum(n2);
        dot   = warp_sum(dot);
        klb   = warp_sum(klb);

        // merge lane-local top-5: 5 rounds of warp argmax, winner pops
        int k = 0;
        float tkl[5];
        #pragma unroll
        for (int r = 0; r < 5; r++) {
            float cand = (k == 0) ? t_0 : (k == 1) ? t_1 : (k == 2) ? t_2
                       : (k == 3) ? t_3 : (k == 4) ? t_4 : -1e30f;
            float best = cand;
            int bl = lane;
            #pragma unroll
            for (int o = 16; o; o >>= 1) {
                float ov = __shfl_xor_sync(0xffffffffu, best, o);
                int   ol = __shfl_xor_sync(0xffffffffu, bl, o);
                if (ov > best || (ov == best && ol < bl)) { best = ov; bl = ol; }
            }
            tkl[r] = best;
            if (lane == bl) k++;
        }

        if (lane == 0) {
            float tk0 = tkl[0], tk1 = tkl[1];
            float mass = tkl[0] + tkl[1] + tkl[2] + tkl[3] + tkl[4];
            float ent  = -LN2F * s_plp;
            float kl   = LN2F * (s_plp - klb);
            float pn   = fmaxf(sqrtf(n2), 1e-8f);
            float mn   = fmaxf(sqrtf(s_glob[2]), 1e-8f);
            float cosv = dot / (pn * mn);
            float* fr = outFeats + (size_t)t * DFEAT;
            fr[0 * 8 + e] = clipf(ent);
            fr[1 * 8 + e] = clipf(mass);
            fr[2 * 8 + e] = clipf(1.0f - mass);
            fr[3 * 8 + e] = clipf(tk0);
            fr[4 * 8 + e] = clipf(tk0 - tk1);
            fr[5 * 8 + e] = clipf(cosv);
            fr[6 * 8 + e] = clipf(kl);
            s_maxp[e] = tk0;
        }
    }
    __syncthreads();

    if (tid == 0) {
        float s = 0.0f;
        #pragma unroll
        for (int e = 0; e < NE; e++) s += s_maxp[e];
        float mean = s * 0.125f;
        float ss = 0.0f;
        #pragma unroll
        for (int e = 0; e < NE; e++) { float d = s_maxp[e] - mean; ss = fmaf(d, d, ss); }
        float stdm = sqrtf(ss * (1.0f / 7.0f));   // ddof=1
        float* fr = outFeats + (size_t)t * DFEAT;
        fr[56] = clipf(-LN2F * s_glob[1]);        // mean entropy
        fr[57] = clipf(s_glob[0] * (1.0f / NC));  // mean class var
        fr[58] = clipf(stdm);                     // std of max probs
    }
}

// ---------------------------------------------------------------------------
// Kernel 2: fused MLP, 16 tokens / block, 256 threads.
// GEMM thread map: (token tt = lane&15, col-group) -> weight loads are
// lane-broadcast (16 lanes share each W address). f32x2 accumulation.
// ---------------------------------------------------------------------------
__global__ __launch_bounds__(256) void mlp_fused(
    const float* __restrict__ feats,
    const float* __restrict__ W1, const float* __restrict__ b1,
    const float* __restrict__ g1, const float* __restrict__ be1,
    const float* __restrict__ W2, const float* __restrict__ b2,
    const float* __restrict__ g2, const float* __restrict__ be2,
    const float* __restrict__ W3, const float* __restrict__ b3,
    float* __restrict__ weights, float* __restrict__ logits)
{
    __shared__ __align__(16) float sfeat[TPB * 60];   // 3.8 KB
    __shared__ __align__(16) float sh[TPB * 260];     // 16.6 KB (h1)
    __shared__ __align__(16) float sh2[TPB * 132];    // 8.4 KB (h2)
    __shared__ float sW3[8 * NH2];                    // 4 KB, transposed [e][k]
    __shared__ float sb3[8];

    const int t0   = blockIdx.x * TPB;
    const int tid  = threadIdx.x;
    const int lane = tid & 31;
    const int w    = tid >> 5;
    const int tt   = lane & 15;
    const int half = lane >> 4;

    // stage feats + W3(transposed) + b3
    {
        const float* src = feats + (size_t)t0 * DFEAT;
        for (int i = tid; i < TPB * DFEAT; i += 256) {
            int T = i / DFEAT, d = i - T * DFEAT;
            sfeat[T * 60 + d] = src[i];
        }
        for (int i = tid; i < NH2 * 8; i += 256) {
            int k = i >> 3, e = i & 7;
            sW3[e * NH2 + k] = W3[i];
        }
        if (tid < 8) sb3[tid] = b3[tid];
    }
    __syncthreads();

    // ---- GEMM1: 16 cols per thread, f32x2 accumulate, broadcast W loads ----
    {
        const int j0 = (w * 2 + half) * 16;
        unsigned long long acc[8];
        #pragma unroll
        for (int i = 0; i < 8; i++) acc[i] = 0ull;

        #pragma unroll 4
        for (int k = 0; k < DFEAT; k++) {
            const float* wr = W1 + k * NH1 + j0;
            F4U2 w0, w1, w2, w3;
            w0.f = *(const float4*)(wr);
            w1.f = *(const float4*)(wr + 4);
            w2.f = *(const float4*)(wr + 8);
            w3.f = *(const float4*)(wr + 12);
            float f = sfeat[tt * 60 + k];
            unsigned long long ff = pack2(f, f);
            ffma2(acc[0], w0.u.x, ff); ffma2(acc[1], w0.u.y, ff);
            ffma2(acc[2], w1.u.x, ff); ffma2(acc[3], w1.u.y, ff);
            ffma2(acc[4], w2.u.x, ff); ffma2(acc[5], w2.u.y, ff);
            ffma2(acc[6], w3.u.x, ff); ffma2(acc[7], w3.u.y, ff);
        }
        #pragma unroll
        for (int m = 0; m < 4; m++) {
            float4 bb = *(const float4*)(b1 + j0 + m * 4);
            float2 lo = unpack2(acc[2 * m]);
            float2 hi = unpack2(acc[2 * m + 1]);
            float4 o;
            o.x = lo.x + bb.x; o.y = lo.y + bb.y;
            o.z = hi.x + bb.z; o.w = hi.y + bb.w;
            *(float4*)(sh + tt * 260 + j0 + m * 4) = o;
        }
    }
    __syncthreads();

    // ---- LN1 + ReLU: warp w handles tokens 2w, 2w+1 ----
    #pragma unroll
    for (int a = 0; a < 2; a++) {
        int T = 2 * w + a;
        float* row = sh + T * 260;
        const int j0 = lane * 8;
        float4 v0 = *(float4*)(row + j0);
        float4 v1 = *(float4*)(row + j0 + 4);
        float s = v0.x + v0.y + v0.z + v0.w + v1.x + v1.y + v1.z + v1.w;
        s = warp_sum(s);
        float mu = s * (1.0f / NH1);
        float vs = 0.0f;
        vs = fmaf(v0.x - mu, v0.x - mu, vs); vs = fmaf(v0.y - mu, v0.y - mu, vs);
        vs = fmaf(v0.z - mu, v0.z - mu, vs); vs = fmaf(v0.w - mu, v0.w - mu, vs);
        vs = fmaf(v1.x - mu, v1.x - mu, vs); vs = fmaf(v1.y - mu, v1.y - mu, vs);
        vs = fmaf(v1.z - mu, v1.z - mu, vs); vs = fmaf(v1.w - mu, v1.w - mu, vs);
        vs = warp_sum(vs);
        float inv = rsqrtf(vs * (1.0f / NH1) + 1e-5f);
        float4 gg0 = *(const float4*)(g1 + j0);
        float4 gg1 = *(const float4*)(g1 + j0 + 4);
        float4 bb0 = *(const float4*)(be1 + j0);
        float4 bb1 = *(const float4*)(be1 + j0 + 4);
        float4 o0, o1;
        o0.x = fmaxf((v0.x - mu) * inv * gg0.x + bb0.x, 0.0f);
        o0.y = fmaxf((v0.y - mu) * inv * gg0.y + bb0.y, 0.0f);
        o0.z = fmaxf((v0.z - mu) * inv * gg0.z + bb0.z, 0.0f);
        o0.w = fmaxf((v0.w - mu) * inv * gg0.w + bb0.w, 0.0f);
        o1.x = fmaxf((v1.x - mu) * inv * gg1.x + bb1.x, 0.0f);
        o1.y = fmaxf((v1.y - mu) * inv * gg1.y + bb1.y, 0.0f);
        o1.z = fmaxf((v1.z - mu) * inv * gg1.z + bb1.z, 0.0f);
        o1.w = fmaxf((v1.w - mu) * inv * gg1.w + bb1.w, 0.0f);
        *(float4*)(row + j0)     = o0;
        *(float4*)(row + j0 + 4) = o1;
    }
    __syncthreads();

    // ---- GEMM2: 8 cols per thread, f32x2, broadcast W loads ----
    {
        const int j0 = (w * 2 + half) * 8;
        unsigned long long acc[4];
        #pragma unroll
        for (int i = 0; i < 4; i++) acc[i] = 0ull;

        const float* frow = sh + tt * 260;
        #pragma unroll 4
        for (int k = 0; k < NH1; k++) {
            const float* wr = W2 + k * NH2 + j0;
            F4U2 w0, w1;
            w0.f = *(const float4*)(wr);
            w1.f = *(const float4*)(wr + 4);
            float f = frow[k];
            unsigned long long ff = pack2(f, f);
            ffma2(acc[0], w0.u.x, ff); ffma2(acc[1], w0.u.y, ff);
            ffma2(acc[2], w1.u.x, ff); ffma2(acc[3], w1.u.y, ff);
        }
        #pragma unroll
        for (int m = 0; m < 2; m++) {
            float4 bb = *(const float4*)(b2 + j0 + m * 4);
            float2 lo = unpack2(acc[2 * m]);
            float2 hi = unpack2(acc[2 * m + 1]);
            float4 o;
            o.x = lo.x + bb.x; o.y = lo.y + bb.y;
            o.z = hi.x + bb.z; o.w = hi.y + bb.w;
            *(float4*)(sh2 + tt * 132 + j0 + m * 4) = o;
        }
    }
    __syncthreads();

    // ---- LN2 + ReLU + GEMM3 + softmax: warp w handles tokens 2w, 2w+1 ----
    #pragma unroll
    for (int a = 0; a < 2; a++) {
        int T = 2 * w + a;
        float* row = sh2 + T * 132;
        const int j0 = lane * 4;
        float4 v = *(float4*)(row + j0);
        float s = v.x + v.y + v.z + v.w;
        s = warp_sum(s);
        float mu = s * (1.0f / NH2);
        float vs = 0.0f;
        vs = fmaf(v.x - mu, v.x - mu, vs); vs = fmaf(v.y - mu, v.y - mu, vs);
        vs = fmaf(v.z - mu, v.z - mu, vs); vs = fmaf(v.w - mu, v.w - mu, vs);
        vs = warp_sum(vs);
        float inv = rsqrtf(vs * (1.0f / NH2) + 1e-5f);
        float4 gg = *(const float4*)(g2 + j0);
        float4 bb = *(const float4*)(be2 + j0);
        float4 h;
        h.x = fmaxf((v.x - mu) * inv * gg.x + bb.x, 0.0f);
        h.y = fmaxf((v.y - mu) * inv * gg.y + bb.y, 0.0f);
        h.z = fmaxf((v.z - mu) * inv * gg.z + bb.z, 0.0f);
        h.w = fmaxf((v.w - mu) * inv * gg.w + bb.w, 0.0f);

        // GEMM3: each lane holds h for k = j0..j0+3
        float acc[8];
        #pragma unroll
        for (int e = 0; e < 8; e++) {
            const float* w3r = sW3 + e * NH2 + j0;
            float t = h.x * w3r[0];
            t = fmaf(h.y, w3r[1], t);
            t = fmaf(h.z, w3r[2], t);
            t = fmaf(h.w, w3r[3], t);
            acc[e] = warp_sum(t);
        }

        if (lane == 0) {
            int tg = t0 + T;
            float lg[8];
            float mx = -1e30f;
            #pragma unroll
            for (int e = 0; e < 8; e++) { lg[e] = acc[e] + sb3[e]; mx = fmaxf(mx, lg[e]); }
            float ex[8];
            float ssum = 0.0f;
            #pragma unroll
            for (int e = 0; e < 8; e++) { ex[e] = __expf(lg[e] - mx); ssum += ex[e]; }
            float invs = 1.0f / ssum;
            float4* lgo = (float4*)(logits + (size_t)tg * 8);
            float4* wgo = (float4*)(weights + (size_t)tg * 8);
            float4 o;
            o.x = lg[0]; o.y = lg[1]; o.z = lg[2]; o.w = lg[3]; lgo[0] = o;
            o.x = lg[4]; o.y = lg[5]; o.z = lg[6]; o.w = lg[7]; lgo[1] = o;
            o.x = ex[0] * invs; o.y = ex[1] * invs; o.z = ex[2] * invs; o.w = ex[3] * invs; wgo[0] = o;
            o.x = ex[4] * invs; o.y = ex[5] * invs; o.z = ex[6] * invs; o.w = ex[7] * invs; wgo[1] = o;
        }
    }
}

// ---------------------------------------------------------------------------
extern "C" void kernel_launch(void* const* d_in, const int* in_sizes, int n_in,
                              void* d_out, int out_size)
{
    const float* post = (const float*)d_in[0];
    const float* W1   = (const float*)d_in[1];
    const float* b1   = (const float*)d_in[2];
    const float* g1   = (const float*)d_in[3];
    const float* be1  = (const float*)d_in[4];
    const float* W2   = (const float*)d_in[5];
    const float* b2   = (const float*)d_in[6];
    const float* g2   = (const float*)d_in[7];
    const float* be2  = (const float*)d_in[8];
    const float* W3   = (const float*)d_in[9];
    const float* b3   = (const float*)d_in[10];

    const int B = in_sizes[0] / (NE * NC);

    float* out     = (float*)d_out;
    float* weights = out;                       // (B, 8)
    float* logits  = out + (size_t)B * 8;       // (B, 8)
    float* feats   = out + (size_t)B * 16;      // (B, 59)

    feat_kernel<<<B, 256>>>(post, feats);
    mlp_fused<<<B / TPB, 256>>>(feats, W1, b1, g1, be1, W2, b2, g2, be2,
                                W3, b3, weights, logits);
}

// round 13
// speedup vs baseline: 1.3369x; 1.2534x over previous
#include <cuda_runtime.h>
#include <math.h>

#define NE 8
#define NC 1000
#define DFEAT 59
#define NH1 256
#define NH2 128
#define TPB 32            // tokens per block (MLP kernel)
#define LN2F 0.69314718055994530942f

__device__ __forceinline__ float clipf(float x) {
    return fminf(fmaxf(x, -100.0f), 100.0f);
}

__device__ __forceinline__ float warp_sum(float v) {
    #pragma unroll
    for (int o = 16; o; o >>= 1) v += __shfl_xor_sync(0xffffffffu, v, o);
    return v;
}

// packed f32x2 FMA (Blackwell): acc.lo += a.lo*b.lo; acc.hi += a.hi*b.hi
__device__ __forceinline__ void ffma2(unsigned long long& acc,
                                      unsigned long long a, unsigned long long b) {
    asm("fma.rn.f32x2 %0, %1, %2, %0;" : "+l"(acc) : "l"(a), "l"(b));
}
__device__ __forceinline__ unsigned long long pack2(float lo, float hi) {
    unsigned long long r;
    asm("mov.b64 %0, {%1, %2};" : "=l"(r) : "f"(lo), "f"(hi));
    return r;
}
__device__ __forceinline__ float2 unpack2(unsigned long long v) {
    float2 r;
    asm("mov.b64 {%0, %1}, %2;" : "=f"(r.x), "=f"(r.y) : "l"(v));
    return r;
}

union F4U2 { float4 f; ulonglong2 u; };

// ---------------------------------------------------------------------------
// Kernel 1: feature extraction (r10 version — known good).
// One block per token, 256 threads (8 warps).
// ---------------------------------------------------------------------------
__global__ __launch_bounds__(256) void feat_kernel(
    const float* __restrict__ post, float* __restrict__ outFeats)
{
    __shared__ __align__(16) float s_mp[1024];
    __shared__ __align__(16) float s_lmp[1024];
    __shared__ float red[24];
    __shared__ float s_maxp[NE];
    __shared__ float s_glob[3];

    const int t    = blockIdx.x;
    const int tid  = threadIdx.x;
    const int lane = tid & 31;
    const int w    = tid >> 5;

    const float4* base = (const float4*)(post + (size_t)t * (NE * NC));

    float a_var = 0.0f, a_ment = 0.0f, a_mn2 = 0.0f;
    if (tid < 250) {
        float4 v = base[tid];
        float sx = v.x, sy = v.y, sz = v.z, sw = v.w;
        float qx = v.x * v.x, qy = v.y * v.y, qz = v.z * v.z, qw = v.w * v.w;
        #pragma unroll
        for (int e = 1; e < 8; e++) {
            v = base[e * 250 + tid];
            sx += v.x; sy += v.y; sz += v.z; sw += v.w;
            qx = fmaf(v.x, v.x, qx); qy = fmaf(v.y, v.y, qy);
            qz = fmaf(v.z, v.z, qz); qw = fmaf(v.w, v.w, qw);
        }
        float m[4] = {sx * 0.125f, sy * 0.125f, sz * 0.125f, sw * 0.125f};
        float q[4] = {qx, qy, qz, qw};
        float lm[4];
        #pragma unroll
        for (int j = 0; j < 4; j++) {
            lm[j] = __log2f(m[j] + 1e-8f);
            a_var += fmaf(-8.0f * m[j], m[j], q[j]) * (1.0f / 7.0f);
            a_ment = fmaf(m[j], lm[j], a_ment);
            a_mn2  = fmaf(m[j], m[j], a_mn2);
        }
        float4 m4; m4.x = m[0];  m4.y = m[1];  m4.z = m[2];  m4.w = m[3];
        float4 l4; l4.x = lm[0]; l4.y = lm[1]; l4.z = lm[2]; l4.w = lm[3];
        ((float4*)s_mp)[tid]  = m4;
        ((float4*)s_lmp)[tid] = l4;
    } else {
        float4 z = make_float4(0.f, 0.f, 0.f, 0.f);
        ((float4*)s_mp)[tid]  = z;
        ((float4*)s_lmp)[tid] = z;
    }
    a_var  = warp_sum(a_var);
    a_ment = warp_sum(a_ment);
    a_mn2  = warp_sum(a_mn2);
    if (lane == 0) { red[w] = a_var; red[8 + w] = a_ment; red[16 + w] = a_mn2; }
    __syncthreads();
    if (tid == 0) {
        float v = 0.0f, me = 0.0f, mn2 = 0.0f;
        #pragma unroll
        for (int i = 0; i < 8; i++) { v += red[i]; me += red[8 + i]; mn2 += red[16 + i]; }
        s_glob[0] = v; s_glob[1] = me; s_glob[2] = mn2;
    }
    __syncthreads();

    {
        const int e = w;
        const float4* prow = base + e * 250;
        unsigned long long splp = 0ull, an2 = 0ull, adot = 0ull, aklb = 0ull;
        float t_0 = -1e30f, t_1 = -1e30f, t_2 = -1e30f, t_3 = -1e30f, t_4 = -1e30f;

        #pragma unroll
        for (int k = 0; k < 8; k++) {
            const int q = lane + 32 * k;
            F4U2 pv;
            if (q < 250) pv.f = __ldg(prow + q);
            else         pv.f = make_float4(0.f, 0.f, 0.f, 0.f);
            F4U2 mv, lv;
            mv.u = ((const ulonglong2*)s_mp)[q];
            lv.u = ((const ulonglong2*)s_lmp)[q];

            float lp0 = __log2f(pv.f.x + 1e-8f);
            float lp1 = __log2f(pv.f.y + 1e-8f);
            float lp2 = __log2f(pv.f.z + 1e-8f);
            float lp3 = __log2f(pv.f.w + 1e-8f);
            unsigned long long lp01 = pack2(lp0, lp1);
            unsigned long long lp23 = pack2(lp2, lp3);

            ffma2(splp, pv.u.x, lp01);   ffma2(splp, pv.u.y, lp23);
            ffma2(an2,  pv.u.x, pv.u.x); ffma2(an2,  pv.u.y, pv.u.y);
            ffma2(adot, pv.u.x, mv.u.x); ffma2(adot, pv.u.y, mv.u.y);
            ffma2(aklb, pv.u.x, lv.u.x); ffma2(aklb, pv.u.y, lv.u.y);

            #define TOP5_INS(P) { \
                float c1 = fminf(t_0, (P)); t_0 = fmaxf(t_0, (P)); \
                float c2 = fminf(t_1, c1);  t_1 = fmaxf(t_1, c1); \
                float c3 = fminf(t_2, c2);  t_2 = fmaxf(t_2, c2); \
                float c4 = fminf(t_3, c3);  t_3 = fmaxf(t_3, c3); \
                t_4 = fmaxf(t_4, c4); }
            TOP5_INS(pv.f.x) TOP5_INS(pv.f.y) TOP5_INS(pv.f.z) TOP5_INS(pv.f.w)
            #undef TOP5_INS
        }

        float2 u;
        u = unpack2(splp); float s_plp = u.x + u.y;
        u = unpack2(an2);  float n2    = u.x + u.y;
        u = unpack2(adot); float dot   = u.x + u.y;
        u = unpack2(aklb); float klb   = u.x + u.y;
        s_plp = warp_sum(s_plp);
        n2    = warp_sum(n2);
        dot   = warp_sum(dot);
        klb   = warp_sum(klb);

        int k = 0;
        float tkl[5];
        #pragma unroll
        for (int r = 0; r < 5; r++) {
            float cand = (k == 0) ? t_0 : (k == 1) ? t_1 : (k == 2) ? t_2
                       : (k == 3) ? t_3 : (k == 4) ? t_4 : -1e30f;
            float best = cand;
            int bl = lane;
            #pragma unroll
            for (int o = 16; o; o >>= 1) {
                float ov = __shfl_xor_sync(0xffffffffu, best, o);
                int   ol = __shfl_xor_sync(0xffffffffu, bl, o);
                if (ov > best || (ov == best && ol < bl)) { best = ov; bl = ol; }
            }
            tkl[r] = best;
            if (lane == bl) k++;
        }

        if (lane == 0) {
            float tk0 = tkl[0], tk1 = tkl[1];
            float mass = tkl[0] + tkl[1] + tkl[2] + tkl[3] + tkl[4];
            float ent  = -LN2F * s_plp;
            float kl   = LN2F * (s_plp - klb);
            float pn   = fmaxf(sqrtf(n2), 1e-8f);
            float mn   = fmaxf(sqrtf(s_glob[2]), 1e-8f);
            float cosv = dot / (pn * mn);
            float* fr = outFeats + (size_t)t * DFEAT;
            fr[0 * 8 + e] = clipf(ent);
            fr[1 * 8 + e] = clipf(mass);
            fr[2 * 8 + e] = clipf(1.0f - mass);
            fr[3 * 8 + e] = clipf(tk0);
            fr[4 * 8 + e] = clipf(tk0 - tk1);
            fr[5 * 8 + e] = clipf(cosv);
            fr[6 * 8 + e] = clipf(kl);
            s_maxp[e] = tk0;
        }
    }
    __syncthreads();

    if (tid == 0) {
        float s = 0.0f;
        #pragma unroll
        for (int e = 0; e < NE; e++) s += s_maxp[e];
        float mean = s * 0.125f;
        float ss = 0.0f;
        #pragma unroll
        for (int e = 0; e < NE; e++) { float d = s_maxp[e] - mean; ss = fmaf(d, d, ss); }
        float stdm = sqrtf(ss * (1.0f / 7.0f));
        float* fr = outFeats + (size_t)t * DFEAT;
        fr[56] = clipf(-LN2F * s_glob[1]);
        fr[57] = clipf(s_glob[0] * (1.0f / NC));
        fr[58] = clipf(stdm);
    }
}

// ---------------------------------------------------------------------------
// Kernel 2: fused MLP v3. 32 tokens / block, 256 threads, 4 blocks/SM forced.
// Layout: warp w owns tokens 4w..4w+3 (r10-style, high FMA:load ratio),
// f32x2 accumulation over column pairs (weights arrive pre-paired via LDG.128),
// transposed feature tile (1 broadcast LDS.128 per k for all 4 tokens).
// ---------------------------------------------------------------------------
__global__ __launch_bounds__(256, 4) void mlp_fused(
    const float* __restrict__ feats,
    const float* __restrict__ W1, const float* __restrict__ b1,
    const float* __restrict__ g1, const float* __restrict__ be1,
    const float* __restrict__ W2, const float* __restrict__ b2,
    const float* __restrict__ g2, const float* __restrict__ be2,
    const float* __restrict__ W3, const float* __restrict__ b3,
    float* __restrict__ weights, float* __restrict__ logits)
{
    __shared__ __align__(16) float sfT[60 * TPB];     // transposed feats [k][token], 7.7 KB
    __shared__ __align__(16) float sh[TPB * 260];     // h1, 33.3 KB
    __shared__ __align__(16) float sh2[TPB * 132];    // h2, 16.9 KB
    __shared__ float sW3[8 * NH2];                    // 4 KB, [e][k]
    __shared__ float sb3[8];

    const int t0   = blockIdx.x * TPB;
    const int tid  = threadIdx.x;
    const int lane = tid & 31;
    const int w    = tid >> 5;

    // stage transposed feats + W3(transposed) + b3
    {
        const float* src = feats + (size_t)t0 * DFEAT;
        for (int i = tid; i < TPB * DFEAT; i += 256) {
            int T = i / DFEAT, d = i - T * DFEAT;
            sfT[d * TPB + T] = src[i];
        }
        for (int i = tid; i < NH2 * 8; i += 256) {
            int k = i >> 3, e = i & 7;
            sW3[e * NH2 + k] = W3[i];
        }
        if (tid < 8) sb3[tid] = b3[tid];
    }
    __syncthreads();

    // ---- GEMM1: warp w -> tokens 4w..4w+3, lane -> cols lane*8..lane*8+7 ----
    {
        const int j0 = lane * 8;
        unsigned long long acc[4][4];   // [token][col-pair]
        #pragma unroll
        for (int a = 0; a < 4; a++)
            #pragma unroll
            for (int b = 0; b < 4; b++) acc[a][b] = 0ull;

        #pragma unroll 2
        for (int k = 0; k < DFEAT; k++) {
            F4U2 wa, wb;
            wa.f = *(const float4*)(W1 + k * NH1 + j0);
            wb.f = *(const float4*)(W1 + k * NH1 + j0 + 4);
            // one broadcast LDS.128: feats of tokens 4w..4w+3 at row k
            float4 fv = *(const float4*)(sfT + k * TPB + 4 * w);
            unsigned long long f0 = pack2(fv.x, fv.x);
            unsigned long long f1 = pack2(fv.y, fv.y);
            unsigned long long f2 = pack2(fv.z, fv.z);
            unsigned long long f3 = pack2(fv.w, fv.w);
            ffma2(acc[0][0], wa.u.x, f0); ffma2(acc[0][1], wa.u.y, f0);
            ffma2(acc[0][2], wb.u.x, f0); ffma2(acc[0][3], wb.u.y, f0);
            ffma2(acc[1][0], wa.u.x, f1); ffma2(acc[1][1], wa.u.y, f1);
            ffma2(acc[1][2], wb.u.x, f1); ffma2(acc[1][3], wb.u.y, f1);
            ffma2(acc[2][0], wa.u.x, f2); ffma2(acc[2][1], wa.u.y, f2);
            ffma2(acc[2][2], wb.u.x, f2); ffma2(acc[2][3], wb.u.y, f2);
            ffma2(acc[3][0], wa.u.x, f3); ffma2(acc[3][1], wa.u.y, f3);
            ffma2(acc[3][2], wb.u.x, f3); ffma2(acc[3][3], wb.u.y, f3);
        }
        float4 ba = *(const float4*)(b1 + j0);
        float4 bb = *(const float4*)(b1 + j0 + 4);
        #pragma unroll
        for (int a = 0; a < 4; a++) {
            int T = 4 * w + a;
            float2 p0 = unpack2(acc[a][0]);
            float2 p1 = unpack2(acc[a][1]);
            float2 p2 = unpack2(acc[a][2]);
            float2 p3 = unpack2(acc[a][3]);
            float4 o0, o1;
            o0.x = p0.x + ba.x; o0.y = p0.y + ba.y;
            o0.z = p1.x + ba.z; o0.w = p1.y + ba.w;
            o1.x = p2.x + bb.x; o1.y = p2.y + bb.y;
            o1.z = p3.x + bb.z; o1.w = p3.y + bb.w;
            *(float4*)(sh + T * 260 + j0)     = o0;
            *(float4*)(sh + T * 260 + j0 + 4) = o1;
        }
    }
    __syncthreads();

    // ---- LN1 + ReLU: warp w handles its own tokens 4w..4w+3 ----
    {
        const int j0 = lane * 8;
        float4 gg0 = *(const float4*)(g1 + j0);
        float4 gg1 = *(const float4*)(g1 + j0 + 4);
        float4 bb0 = *(const float4*)(be1 + j0);
        float4 bb1 = *(const float4*)(be1 + j0 + 4);
        #pragma unroll
        for (int a = 0; a < 4; a++) {
            int T = 4 * w + a;
            float* row = sh + T * 260;
            float4 v0 = *(float4*)(row + j0);
            float4 v1 = *(float4*)(row + j0 + 4);
            float s = v0.x + v0.y + v0.z + v0.w + v1.x + v1.y + v1.z + v1.w;
            s = warp_sum(s);
            float mu = s * (1.0f / NH1);
            float vs = 0.0f;
            vs = fmaf(v0.x - mu, v0.x - mu, vs); vs = fmaf(v0.y - mu, v0.y - mu, vs);
            vs = fmaf(v0.z - mu, v0.z - mu, vs); vs = fmaf(v0.w - mu, v0.w - mu, vs);
            vs = fmaf(v1.x - mu, v1.x - mu, vs); vs = fmaf(v1.y - mu, v1.y - mu, vs);
            vs = fmaf(v1.z - mu, v1.z - mu, vs); vs = fmaf(v1.w - mu, v1.w - mu, vs);
            vs = warp_sum(vs);
            float inv = rsqrtf(vs * (1.0f / NH1) + 1e-5f);
            float4 o0, o1;
            o0.x = fmaxf((v0.x - mu) * inv * gg0.x + bb0.x, 0.0f);
            o0.y = fmaxf((v0.y - mu) * inv * gg0.y + bb0.y, 0.0f);
            o0.z = fmaxf((v0.z - mu) * inv * gg0.z + bb0.z, 0.0f);
            o0.w = fmaxf((v0.w - mu) * inv * gg0.w + bb0.w, 0.0f);
            o1.x = fmaxf((v1.x - mu) * inv * gg1.x + bb1.x, 0.0f);
            o1.y = fmaxf((v1.y - mu) * inv * gg1.y + bb1.y, 0.0f);
            o1.z = fmaxf((v1.z - mu) * inv * gg1.z + bb1.z, 0.0f);
            o1.w = fmaxf((v1.w - mu) * inv * gg1.w + bb1.w, 0.0f);
            *(float4*)(row + j0)     = o0;
            *(float4*)(row + j0 + 4) = o1;
        }
    }
    __syncthreads();

    // ---- GEMM2: warp w -> tokens 4w..4w+3, lane -> cols lane*4..lane*4+3 ----
    {
        const int j0 = lane * 4;
        unsigned long long acc[4][2];   // [token][col-pair]
        #pragma unroll
        for (int a = 0; a < 4; a++) { acc[a][0] = 0ull; acc[a][1] = 0ull; }

        const float* r0 = sh + (4 * w + 0) * 260;
        const float* r1 = sh + (4 * w + 1) * 260;
        const float* r2 = sh + (4 * w + 2) * 260;
        const float* r3 = sh + (4 * w + 3) * 260;

        #pragma unroll 4
        for (int k = 0; k < NH1; k++) {
            F4U2 w4;
            w4.f = *(const float4*)(W2 + k * NH2 + j0);
            unsigned long long f0 = pack2(r0[k], r0[k]);
            unsigned long long f1 = pack2(r1[k], r1[k]);
            unsigned long long f2 = pack2(r2[k], r2[k]);
            unsigned long long f3 = pack2(r3[k], r3[k]);
            ffma2(acc[0][0], w4.u.x, f0); ffma2(acc[0][1], w4.u.y, f0);
            ffma2(acc[1][0], w4.u.x, f1); ffma2(acc[1][1], w4.u.y, f1);
            ffma2(acc[2][0], w4.u.x, f2); ffma2(acc[2][1], w4.u.y, f2);
            ffma2(acc[3][0], w4.u.x, f3); ffma2(acc[3][1], w4.u.y, f3);
        }
        float4 bb = *(const float4*)(b2 + j0);
        #pragma unroll
        for (int a = 0; a < 4; a++) {
            int T = 4 * w + a;
            float2 p0 = unpack2(acc[a][0]);
            float2 p1 = unpack2(acc[a][1]);
            float4 o;
            o.x = p0.x + bb.x; o.y = p0.y + bb.y;
            o.z = p1.x + bb.z; o.w = p1.y + bb.w;
            *(float4*)(sh2 + T * 132 + j0) = o;
        }
    }
    __syncthreads();

    // ---- LN2 + ReLU + GEMM3 + softmax: warp w -> tokens 4w..4w+3 ----
    {
        const int j0 = lane * 4;
        float4 gg = *(const float4*)(g2 + j0);
        float4 bbn = *(const float4*)(be2 + j0);
        #pragma unroll
        for (int a = 0; a < 4; a++) {
            int T = 4 * w + a;
            float* row = sh2 + T * 132;
            float4 v = *(float4*)(row + j0);
            float s = v.x + v.y + v.z + v.w;
            s = warp_sum(s);
            float mu = s * (1.0f / NH2);
            float vs = 0.0f;
            vs = fmaf(v.x - mu, v.x - mu, vs); vs = fmaf(v.y - mu, v.y - mu, vs);
            vs = fmaf(v.z - mu, v.z - mu, vs); vs = fmaf(v.w - mu, v.w - mu, vs);
            vs = warp_sum(vs);
            float inv = rsqrtf(vs * (1.0f / NH2) + 1e-5f);
            float4 h;
            h.x = fmaxf((v.x - mu) * inv * gg.x + bbn.x, 0.0f);
            h.y = fmaxf((v.y - mu) * inv * gg.y + bbn.y, 0.0f);
            h.z = fmaxf((v.z - mu) * inv * gg.z + bbn.z, 0.0f);
            h.w = fmaxf((v.w - mu) * inv * gg.w + bbn.w, 0.0f);

            float acc[8];
            #pragma unroll
            for (int e = 0; e < 8; e++) {
                const float* w3r = sW3 + e * NH2 + j0;
                float t = h.x * w3r[0];
                t = fmaf(h.y, w3r[1], t);
                t = fmaf(h.z, w3r[2], t);
                t = fmaf(h.w, w3r[3], t);
                acc[e] = warp_sum(t);
            }

            if (lane == 0) {
                int tg = t0 + T;
                float lg[8];
                float mx = -1e30f;
                #pragma unroll
                for (int e = 0; e < 8; e++) { lg[e] = acc[e] + sb3[e]; mx = fmaxf(mx, lg[e]); }
                float ex[8];
                float ssum = 0.0f;
                #pragma unroll
                for (int e = 0; e < 8; e++) { ex[e] = __expf(lg[e] - mx); ssum += ex[e]; }
                float invs = 1.0f / ssum;
                float4* lgo = (float4*)(logits + (size_t)tg * 8);
                float4* wgo = (float4*)(weights + (size_t)tg * 8);
                float4 o;
                o.x = lg[0]; o.y = lg[1]; o.z = lg[2]; o.w = lg[3]; lgo[0] = o;
                o.x = lg[4]; o.y = lg[5]; o.z = lg[6]; o.w = lg[7]; lgo[1] = o;
                o.x = ex[0] * invs; o.y = ex[1] * invs; o.z = ex[2] * invs; o.w = ex[3] * invs; wgo[0] = o;
                o.x = ex[4] * invs; o.y = ex[5] * invs; o.z = ex[6] * invs; o.w = ex[7] * invs; wgo[1] = o;
            }
        }
    }
}

// ---------------------------------------------------------------------------
extern "C" void kernel_launch(void* const* d_in, const int* in_sizes, int n_in,
                              void* d_out, int out_size)
{
    const float* post = (const float*)d_in[0];
    const float* W1   = (const float*)d_in[1];
    const float* b1   = (const float*)d_in[2];
    const float* g1   = (const float*)d_in[3];
    const float* be1  = (const float*)d_in[4];
    const float* W2   = (const float*)d_in[5];
    const float* b2   = (const float*)d_in[6];
    const float* g2   = (const float*)d_in[7];
    const float* be2  = (const float*)d_in[8];
    const float* W3   = (const float*)d_in[9];
    const float* b3   = (const float*)d_in[10];

    const int B = in_sizes[0] / (NE * NC);

    float* out     = (float*)d_out;
    float* weights = out;                       // (B, 8)
    float* logits  = out + (size_t)B * 8;       // (B, 8)
    float* feats   = out + (size_t)B * 16;      // (B, 59)

    feat_kernel<<<B, 256>>>(post, feats);
    mlp_fused<<<B / TPB, 256>>>(feats, W1, b1, g1, be1, W2, b2, g2, be2,
                                W3, b3, weights, logits);
}